// round 16
// baseline (speedup 1.0000x reference)
#include <cuda_runtime.h>
#include <cuda_bf16.h>
#include <cuda_fp16.h>
#include <cstdint>

#define B_ 16
#define D_ 128
#define M_ 2048
#define N_ 4096
#define NT 32                 // 128-row tiles per batch
#define CHUNKS 64             // 32 row-tiles x 2 strips (k 0-7 | 8-15(+16))
#define TILEB 16384           // 128 rows * 128 bytes (int8)

__device__ __align__(16) unsigned char g_zn[(size_t)B_ * N_ * D_];
__device__ float g_rowsum[B_ * N_];
__device__ float g_rowpos[B_ * N_];

#define MAGIC_F 12582912.0f
#define MAGIC_I 0x4B400000

// ------------------------------------------------------- normalize + transpose
// (exact R12/R14 version — measured 13.6us, occ 83%)
__global__ void normalize_kernel(const float* __restrict__ Zi,
                                 const float* __restrict__ Zj,
                                 float* __restrict__ out, int out_size) {
    __shared__ float tile[32 * 128];     // [m-lane][d ^ m]
    __shared__ float part[8][32];
    __shared__ float rnorm_s[32];
    const int m0  = blockIdx.x * 32;
    const int src = blockIdx.y;
    const int b   = blockIdx.z;
    const float* Z = src ? Zj : Zi;
    const int tid = threadIdx.x;
    const int tx = tid & 31, ty = tid >> 5;

    const int bid = blockIdx.x + 64 * (src + 2 * b);
    if (tid < 64) {
        int idx = bid * 64 + tid;
        if (idx < B_ * N_) g_rowsum[idx] = 0.f;
        else g_rowpos[idx - B_ * N_] = 0.f;
    }
    if (bid == 0) for (int i = tid; i < out_size; i += 256) out[i] = 0.f;

    const float* base = Z + (size_t)b * D_ * M_ + m0 + tx;
    float ss = 0.f;
#pragma unroll
    for (int d = ty; d < D_; d += 8) {
        float v = base[(size_t)d * M_];
        tile[tx * 128 + (d ^ tx)] = v;
        ss += v * v;
    }
    part[ty][tx] = ss;
    __syncthreads();
    if (ty == 0) {
        float s = 0.f;
#pragma unroll
        for (int k = 0; k < 8; k++) s += part[k][tx];
        rnorm_s[tx] = 127.0f / fmaxf(sqrtf(s), 1e-8f);
    }
    __syncthreads();

    const int q  = tid & 31;
    const int rg = tid >> 5;
    unsigned char* outb = g_zn
        + ((size_t)b * N_ + (size_t)src * M_ + m0) * 128;
#pragma unroll
    for (int it = 0; it < 4; it++) {
        const int r = rg * 4 + it;
        const float rn = rnorm_s[r];
#pragma unroll
        for (int i = 0; i < 4; i++) {
            const int d = q + 32 * i;
            float v = tile[r * 128 + (d ^ r)] * rn;
            int qv;
            asm("cvt.rni.sat.s8.f32 %0, %1;" : "=r"(qv) : "f"(v));
            outb[(size_t)r * 128 + d] = (unsigned char)qv;
        }
    }
}

// ------------------------------------------------------------------- helpers
__device__ __forceinline__ unsigned swz_off(int row, int ch) {
    return (unsigned)(row * 128 + ((ch ^ (row & 7)) << 4));
}
__device__ __forceinline__ void ldsm_x4(unsigned addr, unsigned& r0, unsigned& r1,
                                        unsigned& r2, unsigned& r3) {
    asm volatile("ldmatrix.sync.aligned.m8n8.x4.shared.b16 {%0,%1,%2,%3}, [%4];"
                 : "=r"(r0), "=r"(r1), "=r"(r2), "=r"(r3) : "r"(addr));
}
__device__ __forceinline__ void mma_s8(int* c, const unsigned* a,
                                       unsigned b0, unsigned b1) {
    asm volatile("mma.sync.aligned.m16n8k32.row.col.s32.s8.s8.s32 "
                 "{%0,%1,%2,%3}, {%4,%5,%6,%7}, {%8,%9}, {%0,%1,%2,%3};"
                 : "+r"(c[0]), "+r"(c[1]), "+r"(c[2]), "+r"(c[3])
                 : "r"(a[0]), "r"(a[1]), "r"(a[2]), "r"(a[3]), "r"(b0), "r"(b1));
}
__device__ __forceinline__ void mma_s8_c(int* d, const unsigned* a,
                                         unsigned b0, unsigned b1, int cinit) {
    asm volatile("mma.sync.aligned.m16n8k32.row.col.s32.s8.s8.s32 "
                 "{%0,%1,%2,%3}, {%4,%5,%6,%7}, {%8,%9}, {%10,%10,%10,%10};"
                 : "=r"(d[0]), "=r"(d[1]), "=r"(d[2]), "=r"(d[3])
                 : "r"(a[0]), "r"(a[1]), "r"(a[2]), "r"(a[3]),
                   "r"(b0), "r"(b1), "r"(cinit));
}
__device__ __forceinline__ float ex2f(float x) {
    float y; asm("ex2.approx.f32 %0, %1;" : "=f"(y) : "f"(x)); return y;
}
__device__ __forceinline__ float lg2f(float x) {
    float y; asm("lg2.approx.f32 %0, %1;" : "=f"(y) : "f"(x)); return y;
}
__device__ __forceinline__ unsigned pack_h2(float hi, float lo) {
    unsigned p;
    asm("cvt.rn.f16x2.f32 %0, %1, %2;" : "=r"(p) : "f"(hi), "f"(lo));
    return p;
}
__device__ __forceinline__ unsigned ex2_h2(unsigned x) {
    unsigned y; asm("ex2.approx.f16x2 %0, %1;" : "=r"(y) : "r"(x)); return y;
}
__device__ __forceinline__ unsigned hadd2u(unsigned a, unsigned b) {
    unsigned c; asm("add.rn.f16x2 %0, %1, %2;" : "=r"(c) : "r"(a), "r"(b));
    return c;
}
__device__ __forceinline__ float2 h2_to_f2(unsigned u) {
    __half2 h = *reinterpret_cast<__half2*>(&u);
    return __half22float2(h);
}
__device__ __forceinline__ void cp16(unsigned dst, const void* src) {
    asm volatile("cp.async.cg.shared.global [%0], [%1], 16;"
                 :: "r"(dst), "l"(src) : "memory");
}
#define CP_COMMIT() asm volatile("cp.async.commit_group;" ::: "memory")

__device__ __forceinline__ void load_tile(unsigned sdst, const char* gsrc, int tid) {
#pragma unroll
    for (int it = 0; it < 4; it++) {
        int idx = it * 256 + tid;
        int row = idx >> 3, ch = idx & 7;
        cp16(sdst + swz_off(row, ch), gsrc + row * 128 + ch * 16);
    }
}

// ------------------------------------------------------------------ main pass
// Strips of 8 k-values (nt=8, +k16 on s=1 for ti<16 -> nt=9). One barrier per
// tile; csum parity-buffered; s=0 strips use sA directly as the t=0 (diagonal)
// B tile (no load). Tile-loop body identical to R15.
__global__ __launch_bounds__(256, 2) void simclr_chunk_kernel() {
    extern __shared__ char smem[];          // A 16K | B0 | B1 | B2 (16K each)
    __shared__ float csum[2][4][128];
    __shared__ float asum[128], apos[128];

    const int b = blockIdx.y;
    const int ti = blockIdx.x >> 1;
    const int s  = blockIdx.x & 1;
    const int k0 = s * 8;
    const bool has16 = (s == 1 && ti < 16);
    const int nt = has16 ? 9 : 8;

    const int tid = threadIdx.x;
    const int lane = tid & 31, w = tid >> 5;
    const int rowA = (w >> 1) * 32;
    const int colB = (w & 1) * 64;

    unsigned sA = (unsigned)__cvta_generic_to_shared(smem);
    unsigned sB[3] = {sA + 16384, sA + 32768, sA + 49152};

    if (tid < 128) { asum[tid] = 0.f; apos[tid] = 0.f; }

    const char* zb = (const char*)(g_zn + (size_t)b * N_ * D_);
    // prologue: g0 = {A[, B0]}, g1 = {B1}; thereafter one commit per iteration.
    // s=0: tile 0 is the diagonal -> B0 == A, skip its load entirely.
    load_tile(sA, zb + (size_t)ti * TILEB, tid);
    if (s != 0)
        load_tile(sB[0], zb + (size_t)(((ti + k0) & 31)) * TILEB, tid);
    CP_COMMIT();
    load_tile(sB[1], zb + (size_t)(((ti + k0 + 1) & 31)) * TILEB, tid);
    CP_COMMIT();

    float rs[4] = {0.f, 0.f, 0.f, 0.f};
    float* rowsum_b = g_rowsum + b * N_;
    float* rowpos_b = g_rowpos + b * N_;
    const float K  = 2.885390081777927f / 16129.0f;  // 2*log2(e) / 127^2
    const float C0 = -MAGIC_F * K;

    int pj = 0; bool pdt = true;   // no push before t=1

    for (int t = 0; t < nt; t++) {
        // tile t's load = group t; exactly one group (t+1) may stay pending
        asm volatile("cp.async.wait_group 1;" ::: "memory");
        __syncthreads();   // B[t%3] ready; iter t-1 fully done (csum, ldsm)

        // prefetch tile t+2 into slot (t+2)%3 (consumed at t-1 -> free)
        if (t + 2 < nt)
            load_tile(sB[(t + 2) % 3],
                      zb + (size_t)(((ti + k0 + t + 2) & 31)) * TILEB, tid);
        CP_COMMIT();       // unconditional: keeps group accounting uniform

        // push column sums of tile t-1 (parity (t-1)&1)
        if (t > 0 && !pdt && tid < 128) {
            float (*cp)[128] = csum[(t - 1) & 1];
            float cs = (cp[0][tid] + cp[1][tid]) + (cp[2][tid] + cp[3][tid]);
            atomicAdd(&rowsum_b[pj * 128 + tid], cs);
        }

        const int kk = k0 + t;
        const int j = (ti + kk) & 31;
        const bool dt = (kk == 0);
        const bool pt = (kk == 16);
        const unsigned sBt = dt ? sA : sB[t % 3];

        int acc[2][8][4];
        // k = 0: init via separate-C MMA, C = MAGIC_I (bias baked in)
        {
            unsigned a[2][4], bb[4][4];
            const int ch = (lane >> 4);
            const int rl = lane & 15;
#pragma unroll
            for (int mi = 0; mi < 2; mi++)
                ldsm_x4(sA + swz_off(rowA + mi * 16 + rl, ch),
                        a[mi][0], a[mi][1], a[mi][2], a[mi][3]);
#pragma unroll
            for (int g = 0; g < 4; g++)
                ldsm_x4(sBt + swz_off(colB + g * 16 + rl, ch),
                        bb[g][0], bb[g][1], bb[g][2], bb[g][3]);
#pragma unroll
            for (int mi = 0; mi < 2; mi++)
#pragma unroll
                for (int ng = 0; ng < 8; ng++)
                    mma_s8_c(acc[mi][ng], a[mi],
                             bb[ng >> 1][ng & 1], bb[ng >> 1][(ng & 1) + 2],
                             MAGIC_I);
        }
#pragma unroll
        for (int k = 1; k < 4; k++) {            // k32 per step
            unsigned a[2][4], bb[4][4];
            const int ch = 2 * k + (lane >> 4);
            const int rl = lane & 15;
#pragma unroll
            for (int mi = 0; mi < 2; mi++)
                ldsm_x4(sA + swz_off(rowA + mi * 16 + rl, ch),
                        a[mi][0], a[mi][1], a[mi][2], a[mi][3]);
#pragma unroll
            for (int g = 0; g < 4; g++)
                ldsm_x4(sBt + swz_off(colB + g * 16 + rl, ch),
                        bb[g][0], bb[g][1], bb[g][2], bb[g][3]);
#pragma unroll
            for (int mi = 0; mi < 2; mi++)
#pragma unroll
                for (int ng = 0; ng < 8; ng++)
                    mma_s8(acc[mi][ng], a[mi],
                           bb[ng >> 1][ng & 1], bb[ng >> 1][(ng & 1) + 2]);
        }

        float (*csw)[128] = csum[t & 1];
        if (!dt && !pt) {
            unsigned rowacc[4] = {0u, 0u, 0u, 0u};
            unsigned colacc[8] = {0u, 0u, 0u, 0u, 0u, 0u, 0u, 0u};
#pragma unroll
            for (int mi = 0; mi < 2; mi++)
#pragma unroll
                for (int ng = 0; ng < 8; ng++)
#pragma unroll
                    for (int qh = 0; qh < 2; qh++) {
                        float f0 = fmaf(__int_as_float(acc[mi][ng][2 * qh]), K, C0);
                        float f1 = fmaf(__int_as_float(acc[mi][ng][2 * qh + 1]), K, C0);
                        unsigned e = ex2_h2(pack_h2(f1, f0));
                        rowacc[mi * 2 + qh] = hadd2u(rowacc[mi * 2 + qh], e);
                        colacc[ng] = hadd2u(colacc[ng], e);
                    }
#pragma unroll
            for (int idx = 0; idx < 4; idx++) {
                float2 fr = h2_to_f2(rowacc[idx]);
                rs[idx] += fr.x + fr.y;
            }
#pragma unroll
            for (int ng = 0; ng < 8; ng++) {
                unsigned c = colacc[ng];
                c = hadd2u(c, __shfl_xor_sync(0xffffffffu, c, 4));
                c = hadd2u(c, __shfl_xor_sync(0xffffffffu, c, 8));
                c = hadd2u(c, __shfl_xor_sync(0xffffffffu, c, 16));
                if (lane < 4) {
                    float2 fc = h2_to_f2(c);
                    csw[w >> 1][colB + ng * 8 + lane * 2] = fc.x;
                    csw[w >> 1][colB + ng * 8 + lane * 2 + 1] = fc.y;
                }
            }
        } else {
            // exact f32 path for diagonal / positive tiles
#pragma unroll
            for (int mi = 0; mi < 2; mi++)
#pragma unroll
                for (int ng = 0; ng < 8; ng++)
#pragma unroll
                    for (int q = 0; q < 4; q++) {
                        const int lr = rowA + mi * 16 + (q >> 1) * 8 + (lane >> 2);
                        const int lc = colB + ng * 8 + ((lane & 3) << 1) + (q & 1);
                        float f = __int_as_float(acc[mi][ng][q]);
                        const float dv = fmaf(f, K, C0);
                        if (pt && lr == lc) {
                            atomicAdd(&apos[lr], dv);
                            atomicAdd(&rowpos_b[j * 128 + lr], dv);
                        }
                        acc[mi][ng][q] = __float_as_int(
                            (dt && lr == lc) ? 0.f : ex2f(dv));
                    }
#pragma unroll
            for (int idx = 0; idx < 4; idx++) {
                const int mi = idx >> 1, qh = idx & 1;
                float r = 0.f;
#pragma unroll
                for (int ng = 0; ng < 8; ng++)
                    r += __int_as_float(acc[mi][ng][2 * qh])
                       + __int_as_float(acc[mi][ng][2 * qh + 1]);
                rs[idx] += r;
            }
#pragma unroll
            for (int ng = 0; ng < 8; ng++)
#pragma unroll
                for (int ql = 0; ql < 2; ql++) {
                    float cs = __int_as_float(acc[0][ng][ql])
                             + __int_as_float(acc[0][ng][ql + 2])
                             + __int_as_float(acc[1][ng][ql])
                             + __int_as_float(acc[1][ng][ql + 2]);
                    cs += __shfl_xor_sync(0xffffffffu, cs, 4);
                    cs += __shfl_xor_sync(0xffffffffu, cs, 8);
                    cs += __shfl_xor_sync(0xffffffffu, cs, 16);
                    if (lane < 4)
                        csw[w >> 1][colB + ng * 8 + lane * 2 + ql] = cs;
                }
        }

        pj = j; pdt = dt;
    }

    // flush: push last tile's column sums
    __syncthreads();
    if (!pdt && tid < 128) {
        float (*cp)[128] = csum[(nt - 1) & 1];
        float cs = (cp[0][tid] + cp[1][tid]) + (cp[2][tid] + cp[3][tid]);
        atomicAdd(&rowsum_b[pj * 128 + tid], cs);
    }

    // CTA-end: quad-reduce row partials, combine, push rows of tile ti
#pragma unroll
    for (int idx = 0; idx < 4; idx++) {
        rs[idx] += __shfl_xor_sync(0xffffffffu, rs[idx], 1);
        rs[idx] += __shfl_xor_sync(0xffffffffu, rs[idx], 2);
    }
    if ((lane & 3) == 0) {
#pragma unroll
        for (int idx = 0; idx < 4; idx++)
            atomicAdd(&asum[rowA + (idx >> 1) * 16 + (idx & 1) * 8 + (lane >> 2)],
                      rs[idx]);
    }
    __syncthreads();
    if (tid < 128) {
        atomicAdd(&rowsum_b[ti * 128 + tid], asum[tid]);
        if (has16) atomicAdd(&rowpos_b[ti * 128 + tid], apos[tid]);
    }
}

// -------------------------------------------------------------------- finalize
__global__ void finalize_kernel(float* __restrict__ out) {
    const int r = blockIdx.x * 1024 + threadIdx.x;
    float v = 0.6931471805599453f * (lg2f(g_rowsum[r]) - g_rowpos[r]);
#pragma unroll
    for (int o = 16; o > 0; o >>= 1) v += __shfl_xor_sync(0xffffffffu, v, o);
    __shared__ float red[32];
    const int w = threadIdx.x >> 5;
    if ((threadIdx.x & 31) == 0) red[w] = v;
    __syncthreads();
    if (threadIdx.x < 32) {
        float s = red[threadIdx.x];
#pragma unroll
        for (int o = 16; o > 0; o >>= 1) s += __shfl_xor_sync(0xffffffffu, s, o);
        if (threadIdx.x == 0)
            atomicAdd(out, s * (1.f / ((float)B_ * (float)N_)));
    }
}

// ----------------------------------------------------------------- entry point
extern "C" void kernel_launch(void* const* d_in, const int* in_sizes, int n_in,
                              void* d_out, int out_size) {
    const float* Zi = (const float*)d_in[0];
    const float* Zj = (const float*)d_in[1];
    float* out = (float*)d_out;
    (void)in_sizes; (void)n_in;

    cudaFuncSetAttribute(simclr_chunk_kernel,
                         cudaFuncAttributeMaxDynamicSharedMemorySize, 65536);

    normalize_kernel<<<dim3(M_ / 32, 2, B_), 256>>>(Zi, Zj, out, out_size);
    simclr_chunk_kernel<<<dim3(CHUNKS, B_), 256, 65536>>>();
    finalize_kernel<<<B_ * N_ / 1024, 1024>>>(out);
}

// round 17
// speedup vs baseline: 1.1054x; 1.1054x over previous
#include <cuda_runtime.h>
#include <cuda_bf16.h>
#include <cuda_fp16.h>
#include <cstdint>

#define B_ 16
#define D_ 128
#define M_ 2048
#define N_ 4096
#define NT 32                 // 128-row tiles per batch
#define CHUNKS 128            // 32 row-tiles x 4 strips (circulant k-cover)
#define TILEB 16384           // 128 rows * 128 bytes (int8)

__device__ __align__(16) unsigned char g_zn[(size_t)B_ * N_ * D_];
__device__ float g_rowsum[B_ * N_];
__device__ float g_rowpos[B_ * N_];

#define MAGIC_F 12582912.0f
#define MAGIC_I 0x4B400000

// ------------------------------------------------------- normalize + transpose
// (exact R12/R14 version — measured 13.6us, occ 83%)
__global__ void normalize_kernel(const float* __restrict__ Zi,
                                 const float* __restrict__ Zj,
                                 float* __restrict__ out, int out_size) {
    __shared__ float tile[32 * 128];     // [m-lane][d ^ m]
    __shared__ float part[8][32];
    __shared__ float rnorm_s[32];
    const int m0  = blockIdx.x * 32;
    const int src = blockIdx.y;
    const int b   = blockIdx.z;
    const float* Z = src ? Zj : Zi;
    const int tid = threadIdx.x;
    const int tx = tid & 31, ty = tid >> 5;

    const int bid = blockIdx.x + 64 * (src + 2 * b);
    if (tid < 64) {
        int idx = bid * 64 + tid;
        if (idx < B_ * N_) g_rowsum[idx] = 0.f;
        else g_rowpos[idx - B_ * N_] = 0.f;
    }
    if (bid == 0) for (int i = tid; i < out_size; i += 256) out[i] = 0.f;

    const float* base = Z + (size_t)b * D_ * M_ + m0 + tx;
    float ss = 0.f;
#pragma unroll
    for (int d = ty; d < D_; d += 8) {
        float v = base[(size_t)d * M_];
        tile[tx * 128 + (d ^ tx)] = v;
        ss += v * v;
    }
    part[ty][tx] = ss;
    __syncthreads();
    if (ty == 0) {
        float s = 0.f;
#pragma unroll
        for (int k = 0; k < 8; k++) s += part[k][tx];
        rnorm_s[tx] = 127.0f / fmaxf(sqrtf(s), 1e-8f);
    }
    __syncthreads();

    const int q  = tid & 31;
    const int rg = tid >> 5;
    unsigned char* outb = g_zn
        + ((size_t)b * N_ + (size_t)src * M_ + m0) * 128;
#pragma unroll
    for (int it = 0; it < 4; it++) {
        const int r = rg * 4 + it;
        const float rn = rnorm_s[r];
#pragma unroll
        for (int i = 0; i < 4; i++) {
            const int d = q + 32 * i;
            float v = tile[r * 128 + (d ^ r)] * rn;
            int qv;
            asm("cvt.rni.sat.s8.f32 %0, %1;" : "=r"(qv) : "f"(v));
            outb[(size_t)r * 128 + d] = (unsigned char)qv;
        }
    }
}

// ------------------------------------------------------------------- helpers
__device__ __forceinline__ unsigned swz_off(int row, int ch) {
    return (unsigned)(row * 128 + ((ch ^ (row & 7)) << 4));
}
__device__ __forceinline__ void ldsm_x4(unsigned addr, unsigned& r0, unsigned& r1,
                                        unsigned& r2, unsigned& r3) {
    asm volatile("ldmatrix.sync.aligned.m8n8.x4.shared.b16 {%0,%1,%2,%3}, [%4];"
                 : "=r"(r0), "=r"(r1), "=r"(r2), "=r"(r3) : "r"(addr));
}
__device__ __forceinline__ void mma_s8(int* c, const unsigned* a,
                                       unsigned b0, unsigned b1) {
    asm volatile("mma.sync.aligned.m16n8k32.row.col.s32.s8.s8.s32 "
                 "{%0,%1,%2,%3}, {%4,%5,%6,%7}, {%8,%9}, {%0,%1,%2,%3};"
                 : "+r"(c[0]), "+r"(c[1]), "+r"(c[2]), "+r"(c[3])
                 : "r"(a[0]), "r"(a[1]), "r"(a[2]), "r"(a[3]), "r"(b0), "r"(b1));
}
__device__ __forceinline__ void mma_s8_c(int* d, const unsigned* a,
                                         unsigned b0, unsigned b1, int cinit) {
    asm volatile("mma.sync.aligned.m16n8k32.row.col.s32.s8.s8.s32 "
                 "{%0,%1,%2,%3}, {%4,%5,%6,%7}, {%8,%9}, {%10,%10,%10,%10};"
                 : "=r"(d[0]), "=r"(d[1]), "=r"(d[2]), "=r"(d[3])
                 : "r"(a[0]), "r"(a[1]), "r"(a[2]), "r"(a[3]),
                   "r"(b0), "r"(b1), "r"(cinit));
}
__device__ __forceinline__ float ex2f(float x) {
    float y; asm("ex2.approx.f32 %0, %1;" : "=f"(y) : "f"(x)); return y;
}
__device__ __forceinline__ float lg2f(float x) {
    float y; asm("lg2.approx.f32 %0, %1;" : "=f"(y) : "f"(x)); return y;
}
__device__ __forceinline__ unsigned pack_h2(float hi, float lo) {
    unsigned p;
    asm("cvt.rn.f16x2.f32 %0, %1, %2;" : "=r"(p) : "f"(hi), "f"(lo));
    return p;
}
__device__ __forceinline__ unsigned ex2_h2(unsigned x) {
    unsigned y; asm("ex2.approx.f16x2 %0, %1;" : "=r"(y) : "r"(x)); return y;
}
__device__ __forceinline__ unsigned hadd2u(unsigned a, unsigned b) {
    unsigned c; asm("add.rn.f16x2 %0, %1, %2;" : "=r"(c) : "r"(a), "r"(b));
    return c;
}
__device__ __forceinline__ float2 h2_to_f2(unsigned u) {
    __half2 h = *reinterpret_cast<__half2*>(&u);
    return __half22float2(h);
}
__device__ __forceinline__ void cp16(unsigned dst, const void* src) {
    asm volatile("cp.async.cg.shared.global [%0], [%1], 16;"
                 :: "r"(dst), "l"(src) : "memory");
}
#define CP_COMMIT() asm volatile("cp.async.commit_group;" ::: "memory")

__device__ __forceinline__ void load_tile(unsigned sdst, const char* gsrc, int tid) {
#pragma unroll
    for (int it = 0; it < 4; it++) {
        int idx = it * 256 + tid;
        int row = idx >> 3, ch = idx & 7;
        cp16(sdst + swz_off(row, ch), gsrc + row * 128 + ch * 16);
    }
}

// ------------------------------------------------------------------ main pass
// R15 structure (CHUNKS=128, nt=4/5, one barrier per tile, csum parity) +
// diagonal B-load elision: s=0 strips use sA as the t=0 tile (no B0 load).
__global__ __launch_bounds__(256, 2) void simclr_chunk_kernel() {
    extern __shared__ char smem[];          // A 16K | B0 | B1 | B2 (16K each)
    __shared__ float csum[2][4][128];
    __shared__ float asum[128], apos[128];

    const int b = blockIdx.y;
    const int ti = blockIdx.x >> 2;
    const int s  = blockIdx.x & 3;
    const int k0 = s * 4;
    const bool has16 = (s == 3 && ti < 16);
    const int nt = has16 ? 5 : 4;

    const int tid = threadIdx.x;
    const int lane = tid & 31, w = tid >> 5;
    const int rowA = (w >> 1) * 32;
    const int colB = (w & 1) * 64;

    unsigned sA = (unsigned)__cvta_generic_to_shared(smem);
    unsigned sB[3] = {sA + 16384, sA + 32768, sA + 49152};

    if (tid < 128) { asum[tid] = 0.f; apos[tid] = 0.f; }

    const char* zb = (const char*)(g_zn + (size_t)b * N_ * D_);
    // prologue: g0 = {A[, B0]}, g1 = {B1}; thereafter one commit per iteration.
    // s=0: tile 0 is the diagonal -> B0 == A, skip its load entirely.
    load_tile(sA, zb + (size_t)ti * TILEB, tid);
    if (s != 0)
        load_tile(sB[0], zb + (size_t)(((ti + k0) & 31)) * TILEB, tid);
    CP_COMMIT();
    load_tile(sB[1], zb + (size_t)(((ti + k0 + 1) & 31)) * TILEB, tid);
    CP_COMMIT();

    float rs[4] = {0.f, 0.f, 0.f, 0.f};
    float* rowsum_b = g_rowsum + b * N_;
    float* rowpos_b = g_rowpos + b * N_;
    const float K  = 2.885390081777927f / 16129.0f;  // 2*log2(e) / 127^2
    const float C0 = -MAGIC_F * K;

    int pj = 0; bool pdt = true;   // no push before t=1

    for (int t = 0; t < nt; t++) {
        // tile t's load = group t; exactly one group (t+1) may stay pending
        asm volatile("cp.async.wait_group 1;" ::: "memory");
        __syncthreads();   // B[t%3] ready; iter t-1 fully done (csum, ldsm)

        // prefetch tile t+2 into slot (t+2)%3 (consumed at t-1 -> free)
        if (t + 2 < nt)
            load_tile(sB[(t + 2) % 3],
                      zb + (size_t)(((ti + k0 + t + 2) & 31)) * TILEB, tid);
        CP_COMMIT();       // unconditional: keeps group accounting uniform

        // push column sums of tile t-1 (parity (t-1)&1)
        if (t > 0 && !pdt && tid < 128) {
            float (*cp)[128] = csum[(t - 1) & 1];
            float cs = (cp[0][tid] + cp[1][tid]) + (cp[2][tid] + cp[3][tid]);
            atomicAdd(&rowsum_b[pj * 128 + tid], cs);
        }

        const int kk = k0 + t;
        const int j = (ti + kk) & 31;
        const bool dt = (kk == 0);
        const bool pt = (kk == 16);
        const unsigned sBt = dt ? sA : sB[t % 3];

        int acc[2][8][4];
        // k = 0: init via separate-C MMA, C = MAGIC_I (bias baked in)
        {
            unsigned a[2][4], bb[4][4];
            const int ch = (lane >> 4);
            const int rl = lane & 15;
#pragma unroll
            for (int mi = 0; mi < 2; mi++)
                ldsm_x4(sA + swz_off(rowA + mi * 16 + rl, ch),
                        a[mi][0], a[mi][1], a[mi][2], a[mi][3]);
#pragma unroll
            for (int g = 0; g < 4; g++)
                ldsm_x4(sBt + swz_off(colB + g * 16 + rl, ch),
                        bb[g][0], bb[g][1], bb[g][2], bb[g][3]);
#pragma unroll
            for (int mi = 0; mi < 2; mi++)
#pragma unroll
                for (int ng = 0; ng < 8; ng++)
                    mma_s8_c(acc[mi][ng], a[mi],
                             bb[ng >> 1][ng & 1], bb[ng >> 1][(ng & 1) + 2],
                             MAGIC_I);
        }
#pragma unroll
        for (int k = 1; k < 4; k++) {            // k32 per step
            unsigned a[2][4], bb[4][4];
            const int ch = 2 * k + (lane >> 4);
            const int rl = lane & 15;
#pragma unroll
            for (int mi = 0; mi < 2; mi++)
                ldsm_x4(sA + swz_off(rowA + mi * 16 + rl, ch),
                        a[mi][0], a[mi][1], a[mi][2], a[mi][3]);
#pragma unroll
            for (int g = 0; g < 4; g++)
                ldsm_x4(sBt + swz_off(colB + g * 16 + rl, ch),
                        bb[g][0], bb[g][1], bb[g][2], bb[g][3]);
#pragma unroll
            for (int mi = 0; mi < 2; mi++)
#pragma unroll
                for (int ng = 0; ng < 8; ng++)
                    mma_s8(acc[mi][ng], a[mi],
                           bb[ng >> 1][ng & 1], bb[ng >> 1][(ng & 1) + 2]);
        }

        float (*csw)[128] = csum[t & 1];
        if (!dt && !pt) {
            unsigned rowacc[4] = {0u, 0u, 0u, 0u};
            unsigned colacc[8] = {0u, 0u, 0u, 0u, 0u, 0u, 0u, 0u};
#pragma unroll
            for (int mi = 0; mi < 2; mi++)
#pragma unroll
                for (int ng = 0; ng < 8; ng++)
#pragma unroll
                    for (int qh = 0; qh < 2; qh++) {
                        float f0 = fmaf(__int_as_float(acc[mi][ng][2 * qh]), K, C0);
                        float f1 = fmaf(__int_as_float(acc[mi][ng][2 * qh + 1]), K, C0);
                        unsigned e = ex2_h2(pack_h2(f1, f0));
                        rowacc[mi * 2 + qh] = hadd2u(rowacc[mi * 2 + qh], e);
                        colacc[ng] = hadd2u(colacc[ng], e);
                    }
#pragma unroll
            for (int idx = 0; idx < 4; idx++) {
                float2 fr = h2_to_f2(rowacc[idx]);
                rs[idx] += fr.x + fr.y;
            }
#pragma unroll
            for (int ng = 0; ng < 8; ng++) {
                unsigned c = colacc[ng];
                c = hadd2u(c, __shfl_xor_sync(0xffffffffu, c, 4));
                c = hadd2u(c, __shfl_xor_sync(0xffffffffu, c, 8));
                c = hadd2u(c, __shfl_xor_sync(0xffffffffu, c, 16));
                if (lane < 4) {
                    float2 fc = h2_to_f2(c);
                    csw[w >> 1][colB + ng * 8 + lane * 2] = fc.x;
                    csw[w >> 1][colB + ng * 8 + lane * 2 + 1] = fc.y;
                }
            }
        } else {
            // exact f32 path for diagonal / positive tiles
#pragma unroll
            for (int mi = 0; mi < 2; mi++)
#pragma unroll
                for (int ng = 0; ng < 8; ng++)
#pragma unroll
                    for (int q = 0; q < 4; q++) {
                        const int lr = rowA + mi * 16 + (q >> 1) * 8 + (lane >> 2);
                        const int lc = colB + ng * 8 + ((lane & 3) << 1) + (q & 1);
                        float f = __int_as_float(acc[mi][ng][q]);
                        const float dv = fmaf(f, K, C0);
                        if (pt && lr == lc) {
                            atomicAdd(&apos[lr], dv);
                            atomicAdd(&rowpos_b[j * 128 + lr], dv);
                        }
                        acc[mi][ng][q] = __float_as_int(
                            (dt && lr == lc) ? 0.f : ex2f(dv));
                    }
#pragma unroll
            for (int idx = 0; idx < 4; idx++) {
                const int mi = idx >> 1, qh = idx & 1;
                float r = 0.f;
#pragma unroll
                for (int ng = 0; ng < 8; ng++)
                    r += __int_as_float(acc[mi][ng][2 * qh])
                       + __int_as_float(acc[mi][ng][2 * qh + 1]);
                rs[idx] += r;
            }
#pragma unroll
            for (int ng = 0; ng < 8; ng++)
#pragma unroll
                for (int ql = 0; ql < 2; ql++) {
                    float cs = __int_as_float(acc[0][ng][ql])
                             + __int_as_float(acc[0][ng][ql + 2])
                             + __int_as_float(acc[1][ng][ql])
                             + __int_as_float(acc[1][ng][ql + 2]);
                    cs += __shfl_xor_sync(0xffffffffu, cs, 4);
                    cs += __shfl_xor_sync(0xffffffffu, cs, 8);
                    cs += __shfl_xor_sync(0xffffffffu, cs, 16);
                    if (lane < 4)
                        csw[w >> 1][colB + ng * 8 + lane * 2 + ql] = cs;
                }
        }

        pj = j; pdt = dt;
    }

    // flush: push last tile's column sums
    __syncthreads();
    if (!pdt && tid < 128) {
        float (*cp)[128] = csum[(nt - 1) & 1];
        float cs = (cp[0][tid] + cp[1][tid]) + (cp[2][tid] + cp[3][tid]);
        atomicAdd(&rowsum_b[pj * 128 + tid], cs);
    }

    // CTA-end: quad-reduce row partials, combine, push rows of tile ti
#pragma unroll
    for (int idx = 0; idx < 4; idx++) {
        rs[idx] += __shfl_xor_sync(0xffffffffu, rs[idx], 1);
        rs[idx] += __shfl_xor_sync(0xffffffffu, rs[idx], 2);
    }
    if ((lane & 3) == 0) {
#pragma unroll
        for (int idx = 0; idx < 4; idx++)
            atomicAdd(&asum[rowA + (idx >> 1) * 16 + (idx & 1) * 8 + (lane >> 2)],
                      rs[idx]);
    }
    __syncthreads();
    if (tid < 128) {
        atomicAdd(&rowsum_b[ti * 128 + tid], asum[tid]);
        if (has16) atomicAdd(&rowpos_b[ti * 128 + tid], apos[tid]);
    }
}

// -------------------------------------------------------------------- finalize
__global__ void finalize_kernel(float* __restrict__ out) {
    const int r = blockIdx.x * 1024 + threadIdx.x;
    float v = 0.6931471805599453f * (lg2f(g_rowsum[r]) - g_rowpos[r]);
#pragma unroll
    for (int o = 16; o > 0; o >>= 1) v += __shfl_xor_sync(0xffffffffu, v, o);
    __shared__ float red[32];
    const int w = threadIdx.x >> 5;
    if ((threadIdx.x & 31) == 0) red[w] = v;
    __syncthreads();
    if (threadIdx.x < 32) {
        float s = red[threadIdx.x];
#pragma unroll
        for (int o = 16; o > 0; o >>= 1) s += __shfl_xor_sync(0xffffffffu, s, o);
        if (threadIdx.x == 0)
            atomicAdd(out, s * (1.f / ((float)B_ * (float)N_)));
    }
}

// ----------------------------------------------------------------- entry point
extern "C" void kernel_launch(void* const* d_in, const int* in_sizes, int n_in,
                              void* d_out, int out_size) {
    const float* Zi = (const float*)d_in[0];
    const float* Zj = (const float*)d_in[1];
    float* out = (float*)d_out;
    (void)in_sizes; (void)n_in;

    cudaFuncSetAttribute(simclr_chunk_kernel,
                         cudaFuncAttributeMaxDynamicSharedMemorySize, 65536);

    normalize_kernel<<<dim3(M_ / 32, 2, B_), 256>>>(Zi, Zj, out, out_size);
    simclr_chunk_kernel<<<dim3(CHUNKS, B_), 256, 65536>>>();
    finalize_kernel<<<B_ * N_ / 1024, 1024>>>(out);
}